// round 10
// baseline (speedup 1.0000x reference)
#include <cuda_runtime.h>

// FINAL (converged, R10): loss = M * scale, scale = 1/(999N) + 1/N (host),
// M = #pixels where trunc-index(r) != trunc-index(t).
// Measured-optimal shape: 88 blocks x 256 threads (exact fit, N % 1024 == 0).
// Grid-shape sweep: 176x128 = 5.02us, 88x256 = 4.90-5.22us (noise band),
// 44x512 = 5.54us kernel-internal. One float4-pair per thread, straight-line,
// __ldcg (L1 flushed per launch; inputs L2-resident across graph replays).
// Per-warp REDUX -> fused 64-bit (count<<32 | warps_done) atomic; last warp
// writes M*scale and resets via plain release store (graph replays are
// sequential). Wall time replay-overhead bound: pinned at 6.62-6.66us across
// 6 rounds while kernel-internal moved 5.5->4.9us.

__device__ unsigned long long g_acc = 0ull;  // [count:32 | warps_done:32]

static __device__ __forceinline__ int quant_idx(float x) {
    // match reference: x*1000 - 1, clamp below at 0, truncate (floor for v>=0)
    float v = __fsub_rn(__fmul_rn(x, 1000.0f), 1.0f);
    v = v < 0.0f ? 0.0f : v;
    return (int)v;
}

static __device__ __forceinline__ unsigned int count4(float4 a, float4 b) {
    unsigned int c = 0;
    c += (quant_idx(a.x) != quant_idx(b.x));
    c += (quant_idx(a.y) != quant_idx(b.y));
    c += (quant_idx(a.z) != quant_idx(b.z));
    c += (quant_idx(a.w) != quant_idx(b.w));
    return c;
}

static __device__ __forceinline__ void warp_commit(unsigned int cnt,
                                                   unsigned int total_warps,
                                                   float* out, float scale) {
    cnt = __reduce_add_sync(0xFFFFFFFFu, cnt);
    if ((threadIdx.x & 31) == 0) {
        unsigned long long old =
            atomicAdd(&g_acc, ((unsigned long long)cnt << 32) | 1ull);
        if ((unsigned int)(old & 0xFFFFFFFFull) == total_warps - 1) {
            unsigned int M = (unsigned int)(old >> 32) + cnt;
            out[0] = __fmul_rn((float)M, scale);
            // reset for next replay: plain release store, no atomic round-trip
            asm volatile("st.global.release.gpu.u64 [%0], 0;"
                         :: "l"(&g_acc) : "memory");
        }
    }
}

// Exact-fit path: grid*256 threads == N/4 exactly. Straight-line, no guards.
__global__ void __launch_bounds__(256)
true3d_loss_exact(const float4* __restrict__ r4, const float4* __restrict__ t4,
                  float* __restrict__ out, unsigned int total_warps,
                  float scale) {
    const int i = blockIdx.x * 256 + threadIdx.x;
    float4 a = __ldcg(&r4[i]);
    float4 b = __ldcg(&t4[i]);
    warp_commit(count4(a, b), total_warps, out, scale);
}

// Generic guarded fallback for N not a multiple of 1024.
__global__ void __launch_bounds__(256)
true3d_loss_generic(const float* __restrict__ r, const float* __restrict__ t,
                    float* __restrict__ out, int N, unsigned int total_warps,
                    float scale) {
    const int tid = blockIdx.x * blockDim.x + threadIdx.x;
    const int stride = gridDim.x * blockDim.x;
    const int N4 = N >> 2;
    const float4* __restrict__ r4 = (const float4*)r;
    const float4* __restrict__ t4 = (const float4*)t;

    unsigned int cnt = 0;
    for (int i = tid; i < N4; i += stride)
        cnt += count4(__ldcg(&r4[i]), __ldcg(&t4[i]));
    for (int i = (N4 << 2) + tid; i < N; i += stride)
        cnt += (quant_idx(__ldcg(&r[i])) != quant_idx(__ldcg(&t[i])));

    warp_commit(cnt, total_warps, out, scale);
}

extern "C" void kernel_launch(void* const* d_in, const int* in_sizes, int n_in,
                              void* d_out, int out_size) {
    const float* rec = (const float*)d_in[0];
    const float* tgt = (const float*)d_in[1];
    float* out = (float*)d_out;
    const int N = in_sizes[0];

    const float fN = (float)N;
    const float scale = 1.0f / (999.0f * fN) + 1.0f / fN;

    if (N > 0 && (N & 1023) == 0) {
        const int blocks = N / 1024;                    // 88 for N=90112
        const unsigned int total_warps = (unsigned int)blocks * 8u;
        true3d_loss_exact<<<blocks, 256>>>((const float4*)rec,
                                           (const float4*)tgt, out,
                                           total_warps, scale);
    } else {
        const int threads = 256;
        int blocks = (N / 4 + threads - 1) / threads;
        if (blocks < 1) blocks = 1;
        if (blocks > 1024) blocks = 1024;
        const unsigned int total_warps = (unsigned int)blocks * (threads / 32);
        true3d_loss_generic<<<blocks, threads>>>(rec, tgt, out, N, total_warps,
                                                 scale);
    }
}

// round 11
// speedup vs baseline: 1.0047x; 1.0047x over previous
#include <cuda_runtime.h>

// FINAL-candidate (R11): loss = M * scale, scale = 1/(999N) + 1/N (host),
// M = #pixels where trunc-index(r) != trunc-index(t).
// Measured-optimal shape: 88 blocks x 256 threads (exact fit, N % 1024 == 0);
// sweep: 176x128=5.02us, 88x256=4.90-5.25us, 44x512=5.54us kernel-internal.
// R11 change: warp count via 4 independent ballot+popc (parallel VOTEs,
// lat-4 popc adds) instead of serial per-thread accumulate + REDUX — shaves
// the last dependent ops off the per-warp tail. Per-warp fused 64-bit
// (count<<32 | warps_done) atomic; last warp writes M*scale and resets via
// release store (graph replays are sequential). Wall is replay-overhead
// bound (~6.6-6.9us band across 7 rounds).

__device__ unsigned long long g_acc = 0ull;  // [count:32 | warps_done:32]

static __device__ __forceinline__ int quant_idx(float x) {
    // match reference: x*1000 - 1, clamp below at 0, truncate (floor for v>=0)
    float v = __fsub_rn(__fmul_rn(x, 1000.0f), 1.0f);
    v = v < 0.0f ? 0.0f : v;
    return (int)v;
}

// Warp-total mismatch count via 4 independent ballots (all lanes get total).
static __device__ __forceinline__ unsigned int warp_count4(float4 a, float4 b) {
    unsigned int m0 = __ballot_sync(0xFFFFFFFFu, quant_idx(a.x) != quant_idx(b.x));
    unsigned int m1 = __ballot_sync(0xFFFFFFFFu, quant_idx(a.y) != quant_idx(b.y));
    unsigned int m2 = __ballot_sync(0xFFFFFFFFu, quant_idx(a.z) != quant_idx(b.z));
    unsigned int m3 = __ballot_sync(0xFFFFFFFFu, quant_idx(a.w) != quant_idx(b.w));
    return (unsigned int)(__popc(m0) + __popc(m1) + __popc(m2) + __popc(m3));
}

static __device__ __forceinline__ void lane0_commit(unsigned int warp_total,
                                                    unsigned int total_warps,
                                                    float* out, float scale) {
    if ((threadIdx.x & 31) == 0) {
        unsigned long long old =
            atomicAdd(&g_acc, ((unsigned long long)warp_total << 32) | 1ull);
        if ((unsigned int)(old & 0xFFFFFFFFull) == total_warps - 1) {
            unsigned int M = (unsigned int)(old >> 32) + warp_total;
            out[0] = __fmul_rn((float)M, scale);
            // reset for next replay: plain release store, no atomic round-trip
            asm volatile("st.global.release.gpu.u64 [%0], 0;"
                         :: "l"(&g_acc) : "memory");
        }
    }
}

// Exact-fit path: grid*256 threads == N/4 exactly. Straight-line, no guards.
__global__ void __launch_bounds__(256)
true3d_loss_exact(const float4* __restrict__ r4, const float4* __restrict__ t4,
                  float* __restrict__ out, unsigned int total_warps,
                  float scale) {
    const int i = blockIdx.x * 256 + threadIdx.x;
    float4 a = __ldcg(&r4[i]);
    float4 b = __ldcg(&t4[i]);
    lane0_commit(warp_count4(a, b), total_warps, out, scale);
}

// Generic guarded fallback for N not a multiple of 1024.
__global__ void __launch_bounds__(256)
true3d_loss_generic(const float* __restrict__ r, const float* __restrict__ t,
                    float* __restrict__ out, int N, unsigned int total_warps,
                    float scale) {
    const int tid = blockIdx.x * blockDim.x + threadIdx.x;
    const int stride = gridDim.x * blockDim.x;
    const int N4 = N >> 2;
    const float4* __restrict__ r4 = (const float4*)r;
    const float4* __restrict__ t4 = (const float4*)t;

    unsigned int cnt = 0;
    for (int i = tid; i < N4; i += stride) {
        float4 a = __ldcg(&r4[i]);
        float4 b = __ldcg(&t4[i]);
        cnt += (quant_idx(a.x) != quant_idx(b.x));
        cnt += (quant_idx(a.y) != quant_idx(b.y));
        cnt += (quant_idx(a.z) != quant_idx(b.z));
        cnt += (quant_idx(a.w) != quant_idx(b.w));
    }
    for (int i = (N4 << 2) + tid; i < N; i += stride)
        cnt += (quant_idx(__ldcg(&r[i])) != quant_idx(__ldcg(&t[i])));

    cnt = __reduce_add_sync(0xFFFFFFFFu, cnt);
    lane0_commit(cnt, total_warps, out, scale);
}

extern "C" void kernel_launch(void* const* d_in, const int* in_sizes, int n_in,
                              void* d_out, int out_size) {
    const float* rec = (const float*)d_in[0];
    const float* tgt = (const float*)d_in[1];
    float* out = (float*)d_out;
    const int N = in_sizes[0];

    const float fN = (float)N;
    const float scale = 1.0f / (999.0f * fN) + 1.0f / fN;

    if (N > 0 && (N & 1023) == 0) {
        const int blocks = N / 1024;                    // 88 for N=90112
        const unsigned int total_warps = (unsigned int)blocks * 8u;
        true3d_loss_exact<<<blocks, 256>>>((const float4*)rec,
                                           (const float4*)tgt, out,
                                           total_warps, scale);
    } else {
        const int threads = 256;
        int blocks = (N / 4 + threads - 1) / threads;
        if (blocks < 1) blocks = 1;
        if (blocks > 1024) blocks = 1024;
        const unsigned int total_warps = (unsigned int)blocks * (threads / 32);
        true3d_loss_generic<<<blocks, threads>>>(rec, tgt, out, N, total_warps,
                                                 scale);
    }
}

// round 12
// speedup vs baseline: 1.0385x; 1.0337x over previous
#include <cuda_runtime.h>

// FINAL (converged): loss = M * scale, scale = 1/(999N) + 1/N (host),
// M = #pixels where trunc-index(r) != trunc-index(t).
//
// 11-round record: algorithmic collapse of the 90M-element one-hot loss to a
// scalar mismatch count (1000x work reduction), then latency surgery took the
// kernel 6.27 -> 4.90us. Grid sweep: 176x128=5.02, 88x256=4.90-5.25 (best),
// 44x512=5.54, 88x32=10.5. Reduction sweep: smem-block-reduce ~= per-warp
// atomic ~= ballot+popc (all within noise). Wall pinned at 6.62-6.91us across
// 7 rounds while kernel-internal varied 4.9-5.5 -> replay-overhead bound.
// This variant (REDUX + per-warp fused atomic) holds the best measured wall
// distribution (6.624us mode).
//
// Design: 88 blocks x 256 threads (exact fit, N % 1024 == 0), one float4-pair
// per thread, straight-line, __ldcg (L1 flushed per launch; inputs
// L2-resident across graph replays). Per-warp REDUX -> fused 64-bit
// (count<<32 | warps_done) atomic; last warp writes M*scale and resets via
// release store (graph replays are sequential). Guarded fallback for other N.

__device__ unsigned long long g_acc = 0ull;  // [count:32 | warps_done:32]

static __device__ __forceinline__ int quant_idx(float x) {
    // match reference: x*1000 - 1, clamp below at 0, truncate (floor for v>=0)
    float v = __fsub_rn(__fmul_rn(x, 1000.0f), 1.0f);
    v = v < 0.0f ? 0.0f : v;
    return (int)v;
}

static __device__ __forceinline__ unsigned int count4(float4 a, float4 b) {
    unsigned int c = 0;
    c += (quant_idx(a.x) != quant_idx(b.x));
    c += (quant_idx(a.y) != quant_idx(b.y));
    c += (quant_idx(a.z) != quant_idx(b.z));
    c += (quant_idx(a.w) != quant_idx(b.w));
    return c;
}

static __device__ __forceinline__ void warp_commit(unsigned int cnt,
                                                   unsigned int total_warps,
                                                   float* out, float scale) {
    cnt = __reduce_add_sync(0xFFFFFFFFu, cnt);
    if ((threadIdx.x & 31) == 0) {
        unsigned long long old =
            atomicAdd(&g_acc, ((unsigned long long)cnt << 32) | 1ull);
        if ((unsigned int)(old & 0xFFFFFFFFull) == total_warps - 1) {
            unsigned int M = (unsigned int)(old >> 32) + cnt;
            out[0] = __fmul_rn((float)M, scale);
            // reset for next replay: plain release store, no atomic round-trip
            asm volatile("st.global.release.gpu.u64 [%0], 0;"
                         :: "l"(&g_acc) : "memory");
        }
    }
}

// Exact-fit path: grid*256 threads == N/4 exactly. Straight-line, no guards.
__global__ void __launch_bounds__(256)
true3d_loss_exact(const float4* __restrict__ r4, const float4* __restrict__ t4,
                  float* __restrict__ out, unsigned int total_warps,
                  float scale) {
    const int i = blockIdx.x * 256 + threadIdx.x;
    float4 a = __ldcg(&r4[i]);
    float4 b = __ldcg(&t4[i]);
    warp_commit(count4(a, b), total_warps, out, scale);
}

// Generic guarded fallback for N not a multiple of 1024.
__global__ void __launch_bounds__(256)
true3d_loss_generic(const float* __restrict__ r, const float* __restrict__ t,
                    float* __restrict__ out, int N, unsigned int total_warps,
                    float scale) {
    const int tid = blockIdx.x * blockDim.x + threadIdx.x;
    const int stride = gridDim.x * blockDim.x;
    const int N4 = N >> 2;
    const float4* __restrict__ r4 = (const float4*)r;
    const float4* __restrict__ t4 = (const float4*)t;

    unsigned int cnt = 0;
    for (int i = tid; i < N4; i += stride)
        cnt += count4(__ldcg(&r4[i]), __ldcg(&t4[i]));
    for (int i = (N4 << 2) + tid; i < N; i += stride)
        cnt += (quant_idx(__ldcg(&r[i])) != quant_idx(__ldcg(&t[i])));

    warp_commit(cnt, total_warps, out, scale);
}

extern "C" void kernel_launch(void* const* d_in, const int* in_sizes, int n_in,
                              void* d_out, int out_size) {
    const float* rec = (const float*)d_in[0];
    const float* tgt = (const float*)d_in[1];
    float* out = (float*)d_out;
    const int N = in_sizes[0];

    const float fN = (float)N;
    const float scale = 1.0f / (999.0f * fN) + 1.0f / fN;

    if (N > 0 && (N & 1023) == 0) {
        const int blocks = N / 1024;                    // 88 for N=90112
        const unsigned int total_warps = (unsigned int)blocks * 8u;
        true3d_loss_exact<<<blocks, 256>>>((const float4*)rec,
                                           (const float4*)tgt, out,
                                           total_warps, scale);
    } else {
        const int threads = 256;
        int blocks = (N / 4 + threads - 1) / threads;
        if (blocks < 1) blocks = 1;
        if (blocks > 1024) blocks = 1024;
        const unsigned int total_warps = (unsigned int)blocks * (threads / 32);
        true3d_loss_generic<<<blocks, threads>>>(rec, tgt, out, N, total_warps,
                                                 scale);
    }
}